// round 7
// baseline (speedup 1.0000x reference)
#include <cuda_runtime.h>
#include <cuda_fp16.h>
#include <cstdint>

// ---------------------------------------------------------------------------
// GraphBackboneGCN: 3x (GCNConv + ReLU) + global mean pool.
// R6 (resubmit after infra failure): warp-shuffle scan, scan2 folded into
// scan3, wconv merged into init, int4 edge counting, half-warp-per-edge
// uint4 aggregation.
// ---------------------------------------------------------------------------

#define NMAX 50176
#define EMAX 1048576
#define D 128
#define NGRAPH 512

#define SCAN_T 1024
#define SCAN_V 4
#define SCAN_ELEMS (SCAN_T * SCAN_V)

__device__ __align__(128) __half g_h1[(size_t)NMAX * D];   // agg out (fp16)
__device__ __align__(128) __half g_h2[(size_t)NMAX * D];   // gemm out / gather src
__device__ float g_dinv[NMAX];
__device__ int   g_cnt[NMAX];
__device__ int   g_off[NMAX + 1];
__device__ int   g_bsum[64];
__device__ __align__(128) int2 g_csr[EMAX];   // .x = src, .y = coef bits
__device__ float g_gcnt[NGRAPH];
__device__ __align__(128) uint2 g_wb[3][4096]; // W in mma B-fragment order

// ---------------------------------------------------------------------------
// init: zero counters/out, AND pack all three W into mma B-fragment order.
__global__ void k_init(float* __restrict__ out, int N,
                       const float* __restrict__ W1,
                       const float* __restrict__ W2,
                       const float* __restrict__ W3) {
    int i = blockIdx.x * blockDim.x + threadIdx.x;
    if (i < N) g_cnt[i] = 0;
    if (i < NGRAPH) g_gcnt[i] = 0.f;
    if (i < NGRAPH * D) out[i] = 0.f;
    if (i < 3 * 4096) {
        int layer = i >> 12;
        int idx = i & 4095;
        const float* W = layer == 0 ? W1 : (layer == 1 ? W2 : W3);
        int lane = idx & 31;
        int nt = (idx >> 5) & 15;
        int ks = idx >> 9;
        int tig = lane & 3, gid = lane >> 2;
        int n = nt * 8 + gid;
        int k0 = ks * 16 + tig * 2;
        __half2 b0 = __floats2half2_rn(W[k0 * D + n],       W[(k0 + 1) * D + n]);
        __half2 b1 = __floats2half2_rn(W[(k0 + 8) * D + n], W[(k0 + 9) * D + n]);
        g_wb[layer][idx] = make_uint2(*(unsigned*)&b0, *(unsigned*)&b1);
    }
}

// count in-degree, 4 edges per thread (dst 16B-aligned when E%4==0)
__global__ void k_count4(const int4* __restrict__ dst4, int E4) {
    int i = blockIdx.x * blockDim.x + threadIdx.x;
    if (i < E4) {
        int4 e = __ldg(dst4 + i);
        atomicAdd(&g_cnt[e.x], 1);
        atomicAdd(&g_cnt[e.y], 1);
        atomicAdd(&g_cnt[e.z], 1);
        atomicAdd(&g_cnt[e.w], 1);
    }
}
__global__ void k_count1(const int* __restrict__ dst, int E) {
    int e = blockIdx.x * blockDim.x + threadIdx.x;
    if (e < E) atomicAdd(&g_cnt[dst[e]], 1);
}

// ---------------------------------------------------------------------------
// scan phase 1: warp-shuffle block scan (fused dinv, cnt zeroing, graph counts)
__global__ void __launch_bounds__(SCAN_T)
k_scan1(const int* __restrict__ batch, int N) {
    __shared__ int wsum[32];
    int tid = threadIdx.x, lane = tid & 31, wid = tid >> 5;
    int base = blockIdx.x * SCAN_ELEMS + tid * SCAN_V;
    int v[SCAN_V];
    int sum = 0;
    #pragma unroll
    for (int k = 0; k < SCAN_V; k++) {
        int i = base + k;
        v[k] = (i < N) ? g_cnt[i] : 0;
        if (i < N) {
            g_dinv[i] = rsqrtf((float)(v[k] + 1));
            g_cnt[i] = 0;
            atomicAdd(&g_gcnt[batch[i]], 1.f);
        }
        sum += v[k];
    }
    int inc = sum;
    #pragma unroll
    for (int d2 = 1; d2 < 32; d2 <<= 1) {
        int t = __shfl_up_sync(0xffffffffu, inc, d2);
        if (lane >= d2) inc += t;
    }
    if (lane == 31) wsum[wid] = inc;
    __syncthreads();
    if (wid == 0) {
        int w = wsum[lane];
        #pragma unroll
        for (int d2 = 1; d2 < 32; d2 <<= 1) {
            int t = __shfl_up_sync(0xffffffffu, w, d2);
            if (lane >= d2) w += t;
        }
        wsum[lane] = w;
    }
    __syncthreads();
    int wprefix = (wid == 0) ? 0 : wsum[wid - 1];
    int excl = wprefix + inc - sum;
    #pragma unroll
    for (int k = 0; k < SCAN_V; k++) {
        int i = base + k;
        if (i < N) g_off[i] = excl;
        excl += v[k];
    }
    if (tid == SCAN_T - 1) g_bsum[blockIdx.x] = wprefix + inc;
}

// scan phase 2+3 fused: every block re-scans the (<=32) block sums in-warp.
__global__ void __launch_bounds__(SCAN_T)
k_scan3(int nb, int N) {
    __shared__ int s_add;
    if (threadIdx.x < 32) {
        int v = ((int)threadIdx.x < nb) ? g_bsum[threadIdx.x] : 0;
        #pragma unroll
        for (int d2 = 1; d2 < 32; d2 <<= 1) {
            int t = __shfl_up_sync(0xffffffffu, v, d2);
            if ((int)threadIdx.x >= d2) v += t;
        }
        if (blockIdx.x == 0 && (int)threadIdx.x == nb - 1) g_off[N] = v;
        int want = (blockIdx.x == 0) ? 0 : (blockIdx.x - 1);
        int pv = __shfl_sync(0xffffffffu, v, want);
        if (threadIdx.x == 0) s_add = (blockIdx.x == 0) ? 0 : pv;
    }
    __syncthreads();
    if (blockIdx.x == 0) return;
    int add = s_add;
    int base = blockIdx.x * SCAN_ELEMS + threadIdx.x;
    #pragma unroll
    for (int k = 0; k < SCAN_V; k++) {
        int i = base + k * SCAN_T;
        if (i < N) g_off[i] += add;
    }
}

__global__ void k_fill(const int* __restrict__ src,
                       const int* __restrict__ dst, int E) {
    int e = blockIdx.x * blockDim.x + threadIdx.x;
    if (e >= E) return;
    int d = dst[e];
    int s = src[e];
    int pos = g_off[d] + atomicAdd(&g_cnt[d], 1);
    float coef = g_dinv[s] * g_dinv[d];
    g_csr[pos] = make_int2(s, __float_as_int(coef));
}

// ---------------------------------------------------------------------------
// Tensor-core GEMM: h2[N,128](fp16) = X[N,128] @ W[128,128]
#define XS_STRIDE 136

__global__ void __launch_bounds__(256, 2)
k_gemm(const float* __restrict__ X0, int layer, int N, int use_x0) {
    __shared__ __half Xs[128 * XS_STRIDE];
    int tid = threadIdx.x;
    int lane = tid & 31, wid = tid >> 5;
    int row0 = blockIdx.x * 128;

    if (use_x0) {
        for (int i = tid; i < 128 * 32; i += 256) {
            int r = i >> 5, c4 = i & 31;
            int gr = row0 + r;
            float4 v = make_float4(0.f, 0.f, 0.f, 0.f);
            if (gr < N) v = __ldg((const float4*)(X0 + (size_t)gr * D) + c4);
            __half2 lo = __floats2half2_rn(v.x, v.y);
            __half2 hi = __floats2half2_rn(v.z, v.w);
            *(uint2*)&Xs[r * XS_STRIDE + c4 * 4] =
                make_uint2(*(unsigned*)&lo, *(unsigned*)&hi);
        }
    } else {
        for (int i = tid; i < 128 * 16; i += 256) {
            int r = i >> 4, c8 = i & 15;
            int gr = row0 + r;
            uint4 v = make_uint4(0u, 0u, 0u, 0u);
            if (gr < N) v = __ldg((const uint4*)(g_h1 + (size_t)gr * D) + c8);
            *(uint4*)&Xs[r * XS_STRIDE + c8 * 8] = v;
        }
    }
    __syncthreads();

    float acc[16][4];
    #pragma unroll
    for (int nt = 0; nt < 16; nt++)
        acc[nt][0] = acc[nt][1] = acc[nt][2] = acc[nt][3] = 0.f;

    int a_row = (lane & 7) | (((lane >> 3) & 1) << 3);
    int a_col8 = (lane >> 4) * 8;
    const __half* a_base = &Xs[(wid * 16 + a_row) * XS_STRIDE + a_col8];
    const uint2* Wb = g_wb[layer];

    #pragma unroll
    for (int ks = 0; ks < 8; ks++) {
        uint32_t a0, a1, a2, a3;
        uint32_t addr = (uint32_t)__cvta_generic_to_shared(a_base + ks * 16);
        asm volatile(
            "ldmatrix.sync.aligned.m8n8.x4.shared.b16 {%0,%1,%2,%3}, [%4];"
            : "=r"(a0), "=r"(a1), "=r"(a2), "=r"(a3) : "r"(addr));
        #pragma unroll
        for (int nt = 0; nt < 16; nt++) {
            uint2 b = __ldg(Wb + (ks * 16 + nt) * 32 + lane);
            asm volatile(
                "mma.sync.aligned.m16n8k16.row.col.f32.f16.f16.f32 "
                "{%0,%1,%2,%3},{%4,%5,%6,%7},{%8,%9},{%0,%1,%2,%3};"
                : "+f"(acc[nt][0]), "+f"(acc[nt][1]),
                  "+f"(acc[nt][2]), "+f"(acc[nt][3])
                : "r"(a0), "r"(a1), "r"(a2), "r"(a3), "r"(b.x), "r"(b.y));
        }
    }

    int tig = lane & 3, gid = lane >> 2;
    int r_lo = row0 + wid * 16 + gid;
    int r_hi = r_lo + 8;
    #pragma unroll
    for (int nt = 0; nt < 16; nt++) {
        int col = nt * 8 + tig * 2;
        if (r_lo < N) {
            __half2 h = __floats2half2_rn(acc[nt][0], acc[nt][1]);
            *(unsigned*)&g_h2[(size_t)r_lo * D + col] = *(unsigned*)&h;
        }
        if (r_hi < N) {
            __half2 h = __floats2half2_rn(acc[nt][2], acc[nt][3]);
            *(unsigned*)&g_h2[(size_t)r_hi * D + col] = *(unsigned*)&h;
        }
    }
}

// ---------------------------------------------------------------------------
// Aggregation: half-warp per edge. Lane l16 covers 8 cols (uint4 = 16B).
__device__ __forceinline__ void agg8(float acc[8], int s, float c, int l16) {
    uint4 p = __ldg((const uint4*)(g_h2 + (size_t)s * D) + l16);
    float2 v;
    v = __half22float2(*(const __half2*)&p.x);
    acc[0] = fmaf(c, v.x, acc[0]); acc[1] = fmaf(c, v.y, acc[1]);
    v = __half22float2(*(const __half2*)&p.y);
    acc[2] = fmaf(c, v.x, acc[2]); acc[3] = fmaf(c, v.y, acc[3]);
    v = __half22float2(*(const __half2*)&p.z);
    acc[4] = fmaf(c, v.x, acc[4]); acc[5] = fmaf(c, v.y, acc[5]);
    v = __half22float2(*(const __half2*)&p.w);
    acc[6] = fmaf(c, v.x, acc[6]); acc[7] = fmaf(c, v.y, acc[7]);
}

// Returns accumulated+biased+ReLU'd 8 columns for lane l16 (valid in ALL lanes
// after the cross-half reduction).
__device__ __forceinline__ void agg_node8(float acc[8],
                                          const float* __restrict__ bias,
                                          int n, int hl, int l16) {
    #pragma unroll
    for (int i = 0; i < 8; i++) acc[i] = 0.f;
    float di = g_dinv[n];
    if (hl == 0) agg8(acc, n, di * di, l16);   // self-loop on half 0

    int j0 = g_off[n];
    int deg = g_off[n + 1] - j0;
    int base = 0;
    for (; base + 4 <= deg; base += 4) {
        int2 ea = g_csr[j0 + base + hl];
        int2 eb = g_csr[j0 + base + 2 + hl];
        agg8(acc, ea.x, __int_as_float(ea.y), l16);
        agg8(acc, eb.x, __int_as_float(eb.y), l16);
    }
    for (; base < deg; base += 2) {
        int idx = base + hl;
        if (idx < deg) {
            int2 e = g_csr[j0 + idx];
            agg8(acc, e.x, __int_as_float(e.y), l16);
        }
    }
    // cross-half reduction
    #pragma unroll
    for (int i = 0; i < 8; i++)
        acc[i] += __shfl_xor_sync(0xffffffffu, acc[i], 16);

    float4 b0 = __ldg((const float4*)bias + l16 * 2);
    float4 b1 = __ldg((const float4*)bias + l16 * 2 + 1);
    acc[0] = fmaxf(acc[0] + b0.x, 0.f);
    acc[1] = fmaxf(acc[1] + b0.y, 0.f);
    acc[2] = fmaxf(acc[2] + b0.z, 0.f);
    acc[3] = fmaxf(acc[3] + b0.w, 0.f);
    acc[4] = fmaxf(acc[4] + b1.x, 0.f);
    acc[5] = fmaxf(acc[5] + b1.y, 0.f);
    acc[6] = fmaxf(acc[6] + b1.z, 0.f);
    acc[7] = fmaxf(acc[7] + b1.w, 0.f);
}

// layers 1-2: write h1 (fp16)
__global__ void __launch_bounds__(256)
k_agg(const float* __restrict__ bias, int N) {
    int warp = (blockIdx.x * blockDim.x + threadIdx.x) >> 5;
    int lane = threadIdx.x & 31;
    if (warp >= N) return;
    int hl = lane >> 4, l16 = lane & 15;
    float acc[8];
    agg_node8(acc, bias, warp, hl, l16);
    if (hl == 0) {
        __half2 h0 = __floats2half2_rn(acc[0], acc[1]);
        __half2 h1 = __floats2half2_rn(acc[2], acc[3]);
        __half2 h2 = __floats2half2_rn(acc[4], acc[5]);
        __half2 h3 = __floats2half2_rn(acc[6], acc[7]);
        *(uint4*)(g_h1 + (size_t)warp * D + l16 * 8) =
            make_uint4(*(unsigned*)&h0, *(unsigned*)&h1,
                       *(unsigned*)&h2, *(unsigned*)&h3);
    }
}

// layer 3: fused global mean-pool
__global__ void __launch_bounds__(256)
k_agg_pool(const float* __restrict__ bias, const int* __restrict__ batch,
           float* __restrict__ out, int N) {
    int warp = (blockIdx.x * blockDim.x + threadIdx.x) >> 5;
    int lane = threadIdx.x & 31;
    if (warp >= N) return;
    int hl = lane >> 4, l16 = lane & 15;
    float acc[8];
    agg_node8(acc, bias, warp, hl, l16);
    if (hl == 0) {
        int g = batch[warp];
        float* o = out + (size_t)g * D + l16 * 8;
        #pragma unroll
        for (int i = 0; i < 8; i++) atomicAdd(o + i, acc[i]);
    }
}

__global__ void k_div(float* __restrict__ out) {
    int i = blockIdx.x * blockDim.x + threadIdx.x;
    if (i < NGRAPH * D) out[i] = out[i] / fmaxf(g_gcnt[i >> 7], 1.f);
}

// ---------------------------------------------------------------------------
extern "C" void kernel_launch(void* const* d_in, const int* in_sizes, int n_in,
                              void* d_out, int out_size) {
    const float* x  = (const float*)d_in[0];
    // d_in[1] = edge_attr (unused)
    const float* W1 = (const float*)d_in[2];
    const float* b1 = (const float*)d_in[3];
    const float* W2 = (const float*)d_in[4];
    const float* b2 = (const float*)d_in[5];
    const float* W3 = (const float*)d_in[6];
    const float* b3 = (const float*)d_in[7];
    const int* ei    = (const int*)d_in[8];
    const int* batch = (const int*)d_in[9];
    float* out = (float*)d_out;

    int N = in_sizes[0] / D;
    int E = in_sizes[8] / 2;
    const int* src = ei;
    const int* dst = ei + E;

    int span = N > NGRAPH * D ? N : NGRAPH * D;
    int initb = (span + 255) / 256;
    int eb = (E + 255) / 256;
    int gb = (N + 127) / 128;
    int ab = ((N * 32) + 255) / 256;
    int sb = (N + SCAN_ELEMS - 1) / SCAN_ELEMS;

    // preprocessing
    k_init<<<initb, 256>>>(out, N, W1, W2, W3);
    bool vec4 = (E % 4 == 0) && ((((uintptr_t)dst) & 15) == 0);
    if (vec4) {
        int E4 = E / 4;
        k_count4<<<(E4 + 255) / 256, 256>>>((const int4*)dst, E4);
    } else {
        k_count1<<<eb, 256>>>(dst, E);
    }
    k_scan1<<<sb, SCAN_T>>>(batch, N);
    k_scan3<<<sb, SCAN_T>>>(sb, N);
    k_fill<<<eb, 256>>>(src, dst, E);

    // layer 1: x -> h1
    k_gemm<<<gb, 256>>>(x, 0, N, 1);
    k_agg<<<ab, 256>>>(b1, N);
    // layer 2: h1 -> h1
    k_gemm<<<gb, 256>>>(x, 1, N, 0);
    k_agg<<<ab, 256>>>(b2, N);
    // layer 3: h1 -> out (fused pool)
    k_gemm<<<gb, 256>>>(x, 2, N, 0);
    k_agg_pool<<<ab, 256>>>(b3, batch, out, N);

    k_div<<<(NGRAPH * D + 255) / 256, 256>>>(out);
}

// round 8
// speedup vs baseline: 1.2604x; 1.2604x over previous
#include <cuda_runtime.h>
#include <cuda_fp16.h>
#include <cstdint>

// ---------------------------------------------------------------------------
// GraphBackboneGCN: 3x (GCNConv + ReLU) + global mean pool.
// R8: R5's proven warp-per-node aggregation (half-warp variant regressed)
//     + R6 preprocessing (shuffle scan, folded scan3, merged init, int4 count).
// ---------------------------------------------------------------------------

#define NMAX 50176
#define EMAX 1048576
#define D 128
#define NGRAPH 512

#define SCAN_T 1024
#define SCAN_V 4
#define SCAN_ELEMS (SCAN_T * SCAN_V)

__device__ __align__(128) __half g_h1[(size_t)NMAX * D];   // agg out (fp16)
__device__ __align__(128) __half g_h2[(size_t)NMAX * D];   // gemm out / gather src
__device__ float g_dinv[NMAX];
__device__ int   g_cnt[NMAX];
__device__ int   g_off[NMAX + 1];
__device__ int   g_bsum[64];
__device__ __align__(128) int2 g_csr[EMAX];   // .x = src, .y = coef bits
__device__ float g_gcnt[NGRAPH];
__device__ __align__(128) uint2 g_wb[3][4096]; // W in mma B-fragment order

// ---------------------------------------------------------------------------
// init: zero counters/out, AND pack all three W into mma B-fragment order.
__global__ void k_init(float* __restrict__ out, int N,
                       const float* __restrict__ W1,
                       const float* __restrict__ W2,
                       const float* __restrict__ W3) {
    int i = blockIdx.x * blockDim.x + threadIdx.x;
    if (i < N) g_cnt[i] = 0;
    if (i < NGRAPH) g_gcnt[i] = 0.f;
    if (i < NGRAPH * D) out[i] = 0.f;
    if (i < 3 * 4096) {
        int layer = i >> 12;
        int idx = i & 4095;
        const float* W = layer == 0 ? W1 : (layer == 1 ? W2 : W3);
        int lane = idx & 31;
        int nt = (idx >> 5) & 15;
        int ks = idx >> 9;
        int tig = lane & 3, gid = lane >> 2;
        int n = nt * 8 + gid;
        int k0 = ks * 16 + tig * 2;
        __half2 b0 = __floats2half2_rn(W[k0 * D + n],       W[(k0 + 1) * D + n]);
        __half2 b1 = __floats2half2_rn(W[(k0 + 8) * D + n], W[(k0 + 9) * D + n]);
        g_wb[layer][idx] = make_uint2(*(unsigned*)&b0, *(unsigned*)&b1);
    }
}

// count in-degree, 4 edges per thread
__global__ void k_count4(const int4* __restrict__ dst4, int E4) {
    int i = blockIdx.x * blockDim.x + threadIdx.x;
    if (i < E4) {
        int4 e = __ldg(dst4 + i);
        atomicAdd(&g_cnt[e.x], 1);
        atomicAdd(&g_cnt[e.y], 1);
        atomicAdd(&g_cnt[e.z], 1);
        atomicAdd(&g_cnt[e.w], 1);
    }
}
__global__ void k_count1(const int* __restrict__ dst, int E) {
    int e = blockIdx.x * blockDim.x + threadIdx.x;
    if (e < E) atomicAdd(&g_cnt[dst[e]], 1);
}

// ---------------------------------------------------------------------------
// scan phase 1: warp-shuffle block scan (fused dinv, cnt zeroing, graph counts)
__global__ void __launch_bounds__(SCAN_T)
k_scan1(const int* __restrict__ batch, int N) {
    __shared__ int wsum[32];
    int tid = threadIdx.x, lane = tid & 31, wid = tid >> 5;
    int base = blockIdx.x * SCAN_ELEMS + tid * SCAN_V;
    int v[SCAN_V];
    int sum = 0;
    #pragma unroll
    for (int k = 0; k < SCAN_V; k++) {
        int i = base + k;
        v[k] = (i < N) ? g_cnt[i] : 0;
        if (i < N) {
            g_dinv[i] = rsqrtf((float)(v[k] + 1));
            g_cnt[i] = 0;
            atomicAdd(&g_gcnt[batch[i]], 1.f);
        }
        sum += v[k];
    }
    int inc = sum;
    #pragma unroll
    for (int d2 = 1; d2 < 32; d2 <<= 1) {
        int t = __shfl_up_sync(0xffffffffu, inc, d2);
        if (lane >= d2) inc += t;
    }
    if (lane == 31) wsum[wid] = inc;
    __syncthreads();
    if (wid == 0) {
        int w = wsum[lane];
        #pragma unroll
        for (int d2 = 1; d2 < 32; d2 <<= 1) {
            int t = __shfl_up_sync(0xffffffffu, w, d2);
            if (lane >= d2) w += t;
        }
        wsum[lane] = w;
    }
    __syncthreads();
    int wprefix = (wid == 0) ? 0 : wsum[wid - 1];
    int excl = wprefix + inc - sum;
    #pragma unroll
    for (int k = 0; k < SCAN_V; k++) {
        int i = base + k;
        if (i < N) g_off[i] = excl;
        excl += v[k];
    }
    if (tid == SCAN_T - 1) g_bsum[blockIdx.x] = wprefix + inc;
}

// scan phase 2+3 fused: every block re-scans the (<=32) block sums in-warp.
__global__ void __launch_bounds__(SCAN_T)
k_scan3(int nb, int N) {
    __shared__ int s_add;
    if (threadIdx.x < 32) {
        int v = ((int)threadIdx.x < nb) ? g_bsum[threadIdx.x] : 0;
        #pragma unroll
        for (int d2 = 1; d2 < 32; d2 <<= 1) {
            int t = __shfl_up_sync(0xffffffffu, v, d2);
            if ((int)threadIdx.x >= d2) v += t;
        }
        if (blockIdx.x == 0 && (int)threadIdx.x == nb - 1) g_off[N] = v;
        int want = (blockIdx.x == 0) ? 0 : (blockIdx.x - 1);
        int pv = __shfl_sync(0xffffffffu, v, want);
        if (threadIdx.x == 0) s_add = (blockIdx.x == 0) ? 0 : pv;
    }
    __syncthreads();
    if (blockIdx.x == 0) return;
    int add = s_add;
    int base = blockIdx.x * SCAN_ELEMS + threadIdx.x;
    #pragma unroll
    for (int k = 0; k < SCAN_V; k++) {
        int i = base + k * SCAN_T;
        if (i < N) g_off[i] += add;
    }
}

__global__ void k_fill(const int* __restrict__ src,
                       const int* __restrict__ dst, int E) {
    int e = blockIdx.x * blockDim.x + threadIdx.x;
    if (e >= E) return;
    int d = dst[e];
    int s = src[e];
    int pos = g_off[d] + atomicAdd(&g_cnt[d], 1);
    float coef = g_dinv[s] * g_dinv[d];
    g_csr[pos] = make_int2(s, __float_as_int(coef));
}

// ---------------------------------------------------------------------------
// Tensor-core GEMM: h2[N,128](fp16) = X[N,128] @ W[128,128]
#define XS_STRIDE 136

__global__ void __launch_bounds__(256, 2)
k_gemm(const float* __restrict__ X0, int layer, int N, int use_x0) {
    __shared__ __half Xs[128 * XS_STRIDE];
    int tid = threadIdx.x;
    int lane = tid & 31, wid = tid >> 5;
    int row0 = blockIdx.x * 128;

    if (use_x0) {
        for (int i = tid; i < 128 * 32; i += 256) {
            int r = i >> 5, c4 = i & 31;
            int gr = row0 + r;
            float4 v = make_float4(0.f, 0.f, 0.f, 0.f);
            if (gr < N) v = __ldg((const float4*)(X0 + (size_t)gr * D) + c4);
            __half2 lo = __floats2half2_rn(v.x, v.y);
            __half2 hi = __floats2half2_rn(v.z, v.w);
            *(uint2*)&Xs[r * XS_STRIDE + c4 * 4] =
                make_uint2(*(unsigned*)&lo, *(unsigned*)&hi);
        }
    } else {
        for (int i = tid; i < 128 * 16; i += 256) {
            int r = i >> 4, c8 = i & 15;
            int gr = row0 + r;
            uint4 v = make_uint4(0u, 0u, 0u, 0u);
            if (gr < N) v = __ldg((const uint4*)(g_h1 + (size_t)gr * D) + c8);
            *(uint4*)&Xs[r * XS_STRIDE + c8 * 8] = v;
        }
    }
    __syncthreads();

    float acc[16][4];
    #pragma unroll
    for (int nt = 0; nt < 16; nt++)
        acc[nt][0] = acc[nt][1] = acc[nt][2] = acc[nt][3] = 0.f;

    int a_row = (lane & 7) | (((lane >> 3) & 1) << 3);
    int a_col8 = (lane >> 4) * 8;
    const __half* a_base = &Xs[(wid * 16 + a_row) * XS_STRIDE + a_col8];
    const uint2* Wb = g_wb[layer];

    #pragma unroll
    for (int ks = 0; ks < 8; ks++) {
        uint32_t a0, a1, a2, a3;
        uint32_t addr = (uint32_t)__cvta_generic_to_shared(a_base + ks * 16);
        asm volatile(
            "ldmatrix.sync.aligned.m8n8.x4.shared.b16 {%0,%1,%2,%3}, [%4];"
            : "=r"(a0), "=r"(a1), "=r"(a2), "=r"(a3) : "r"(addr));
        #pragma unroll
        for (int nt = 0; nt < 16; nt++) {
            uint2 b = __ldg(Wb + (ks * 16 + nt) * 32 + lane);
            asm volatile(
                "mma.sync.aligned.m16n8k16.row.col.f32.f16.f16.f32 "
                "{%0,%1,%2,%3},{%4,%5,%6,%7},{%8,%9},{%0,%1,%2,%3};"
                : "+f"(acc[nt][0]), "+f"(acc[nt][1]),
                  "+f"(acc[nt][2]), "+f"(acc[nt][3])
                : "r"(a0), "r"(a1), "r"(a2), "r"(a3), "r"(b.x), "r"(b.y));
        }
    }

    int tig = lane & 3, gid = lane >> 2;
    int r_lo = row0 + wid * 16 + gid;
    int r_hi = r_lo + 8;
    #pragma unroll
    for (int nt = 0; nt < 16; nt++) {
        int col = nt * 8 + tig * 2;
        if (r_lo < N) {
            __half2 h = __floats2half2_rn(acc[nt][0], acc[nt][1]);
            *(unsigned*)&g_h2[(size_t)r_lo * D + col] = *(unsigned*)&h;
        }
        if (r_hi < N) {
            __half2 h = __floats2half2_rn(acc[nt][2], acc[nt][3]);
            *(unsigned*)&g_h2[(size_t)r_hi * D + col] = *(unsigned*)&h;
        }
    }
}

// ---------------------------------------------------------------------------
// Aggregation (R5-proven): warp per node, lane covers 4 cols (uint2 = 8B).
__device__ __forceinline__ void agg_edge(float4& acc, const __half* T,
                                         int s, float c, int lane) {
    uint2 p = __ldg((const uint2*)(T + (size_t)s * D) + lane);
    float2 v0 = __half22float2(*(const __half2*)&p.x);
    float2 v1 = __half22float2(*(const __half2*)&p.y);
    acc.x = fmaf(c, v0.x, acc.x);
    acc.y = fmaf(c, v0.y, acc.y);
    acc.z = fmaf(c, v1.x, acc.z);
    acc.w = fmaf(c, v1.y, acc.w);
}

__device__ __forceinline__ float4 agg_node(const float* __restrict__ bias,
                                           int n, int lane) {
    const __half* T = g_h2;
    float di = g_dinv[n];
    float cs = di * di;
    float4 acc = make_float4(0.f, 0.f, 0.f, 0.f);
    agg_edge(acc, T, n, cs, lane);   // self-loop

    int j = g_off[n], end = g_off[n + 1];
    for (; j + 4 <= end; j += 4) {
        int2 e0 = g_csr[j + 0];
        int2 e1 = g_csr[j + 1];
        int2 e2 = g_csr[j + 2];
        int2 e3 = g_csr[j + 3];
        agg_edge(acc, T, e0.x, __int_as_float(e0.y), lane);
        agg_edge(acc, T, e1.x, __int_as_float(e1.y), lane);
        agg_edge(acc, T, e2.x, __int_as_float(e2.y), lane);
        agg_edge(acc, T, e3.x, __int_as_float(e3.y), lane);
    }
    for (; j < end; j++) {
        int2 e = g_csr[j];
        agg_edge(acc, T, e.x, __int_as_float(e.y), lane);
    }

    float4 b = __ldg((const float4*)bias + lane);
    acc.x = fmaxf(acc.x + b.x, 0.f);
    acc.y = fmaxf(acc.y + b.y, 0.f);
    acc.z = fmaxf(acc.z + b.z, 0.f);
    acc.w = fmaxf(acc.w + b.w, 0.f);
    return acc;
}

// layers 1-2: write h1 (fp16)
__global__ void __launch_bounds__(256)
k_agg(const float* __restrict__ bias, int N) {
    int warp = (blockIdx.x * blockDim.x + threadIdx.x) >> 5;
    int lane = threadIdx.x & 31;
    if (warp >= N) return;
    float4 acc = agg_node(bias, warp, lane);
    __half2 lo = __floats2half2_rn(acc.x, acc.y);
    __half2 hi = __floats2half2_rn(acc.z, acc.w);
    *(uint2*)(g_h1 + (size_t)warp * D + lane * 4) =
        make_uint2(*(unsigned*)&lo, *(unsigned*)&hi);
}

// layer 3: fused global mean-pool
__global__ void __launch_bounds__(256)
k_agg_pool(const float* __restrict__ bias, const int* __restrict__ batch,
           float* __restrict__ out, int N) {
    int warp = (blockIdx.x * blockDim.x + threadIdx.x) >> 5;
    int lane = threadIdx.x & 31;
    if (warp >= N) return;
    float4 acc = agg_node(bias, warp, lane);
    int g = batch[warp];
    float* o = out + (size_t)g * D + lane * 4;
    atomicAdd(o + 0, acc.x);
    atomicAdd(o + 1, acc.y);
    atomicAdd(o + 2, acc.z);
    atomicAdd(o + 3, acc.w);
}

__global__ void k_div(float* __restrict__ out) {
    int i = blockIdx.x * blockDim.x + threadIdx.x;
    if (i < NGRAPH * D) out[i] = out[i] / fmaxf(g_gcnt[i >> 7], 1.f);
}

// ---------------------------------------------------------------------------
extern "C" void kernel_launch(void* const* d_in, const int* in_sizes, int n_in,
                              void* d_out, int out_size) {
    const float* x  = (const float*)d_in[0];
    // d_in[1] = edge_attr (unused)
    const float* W1 = (const float*)d_in[2];
    const float* b1 = (const float*)d_in[3];
    const float* W2 = (const float*)d_in[4];
    const float* b2 = (const float*)d_in[5];
    const float* W3 = (const float*)d_in[6];
    const float* b3 = (const float*)d_in[7];
    const int* ei    = (const int*)d_in[8];
    const int* batch = (const int*)d_in[9];
    float* out = (float*)d_out;

    int N = in_sizes[0] / D;
    int E = in_sizes[8] / 2;
    const int* src = ei;
    const int* dst = ei + E;

    int span = N > NGRAPH * D ? N : NGRAPH * D;
    int initb = (span + 255) / 256;
    int eb = (E + 255) / 256;
    int gb = (N + 127) / 128;
    int ab = ((N * 32) + 255) / 256;
    int sb = (N + SCAN_ELEMS - 1) / SCAN_ELEMS;

    // preprocessing
    k_init<<<initb, 256>>>(out, N, W1, W2, W3);
    bool vec4 = (E % 4 == 0) && ((((uintptr_t)dst) & 15) == 0);
    if (vec4) {
        int E4 = E / 4;
        k_count4<<<(E4 + 255) / 256, 256>>>((const int4*)dst, E4);
    } else {
        k_count1<<<eb, 256>>>(dst, E);
    }
    k_scan1<<<sb, SCAN_T>>>(batch, N);
    k_scan3<<<sb, SCAN_T>>>(sb, N);
    k_fill<<<eb, 256>>>(src, dst, E);

    // layer 1: x -> h1
    k_gemm<<<gb, 256>>>(x, 0, N, 1);
    k_agg<<<ab, 256>>>(b1, N);
    // layer 2: h1 -> h1
    k_gemm<<<gb, 256>>>(x, 1, N, 0);
    k_agg<<<ab, 256>>>(b2, N);
    // layer 3: h1 -> out (fused pool)
    k_gemm<<<gb, 256>>>(x, 2, N, 0);
    k_agg_pool<<<ab, 256>>>(b3, batch, out, N);

    k_div<<<(NGRAPH * D + 255) / 256, 256>>>(out);
}